// round 1
// baseline (speedup 1.0000x reference)
#include <cuda_runtime.h>
#include <cuda_bf16.h>
#include <math.h>

#define B_  8
#define S_  2048
#define E_  1024
#define H_  64
#define M_  (B_ * S_)        // 16384 rows
#define NS  4                // key-range splits
#define QB  128              // queries per attention block
#define TK  8                // key tile rows

// ---------------- scratch (static device globals; no allocation) -------------
__device__ float g_k[M_ * H_];
__device__ float g_q[M_ * H_];
__device__ float g_v[M_ * H_];
__device__ float g_po[NS * M_ * H_];   // partial O (unnormalized)
__device__ float g_pm[NS * M_];        // partial running max
__device__ float g_pl[NS * M_];        // partial running sum

// ---------------- QKV projection: out = x @ W (M x 1024 @ 1024 x 64) ---------
__global__ __launch_bounds__(256) void proj_kernel(
    const float* __restrict__ x,
    const float* __restrict__ Wk,
    const float* __restrict__ Wq,
    const float* __restrict__ Wv)
{
    const float* W;
    float* out;
    float scale = 1.0f;
    if (blockIdx.y == 0)      { W = Wk; out = g_k; }
    else if (blockIdx.y == 1) { W = Wq; out = g_q; scale = 0.125f; } // 1/sqrt(64)
    else                      { W = Wv; out = g_v; }

    __shared__ float As[64][16];   // [m][k]
    __shared__ float Bs[16][64];   // [k][n]

    const int tid = threadIdx.x;           // 256 threads
    const int tx = tid & 15;               // col group
    const int ty = tid >> 4;               // row group
    const int m0 = blockIdx.x * 64;

    float acc[4][4];
    #pragma unroll
    for (int i = 0; i < 4; i++)
        #pragma unroll
        for (int j = 0; j < 4; j++) acc[i][j] = 0.0f;

    for (int k0 = 0; k0 < E_; k0 += 16) {
        // load x tile: 64 rows x 16 k
        {
            int row = tid >> 2, quad = tid & 3;
            float4 va = *(const float4*)&x[(size_t)(m0 + row) * E_ + k0 + quad * 4];
            *(float4*)&As[row][quad * 4] = va;
        }
        // load W tile: 16 k x 64 n
        {
            int kr = tid >> 4, c = (tid & 15) * 4;
            float4 vb = *(const float4*)&W[(size_t)(k0 + kr) * H_ + c];
            *(float4*)&Bs[kr][c] = vb;
        }
        __syncthreads();

        #pragma unroll
        for (int kk = 0; kk < 16; kk++) {
            float a0 = As[ty * 4 + 0][kk];
            float a1 = As[ty * 4 + 1][kk];
            float a2 = As[ty * 4 + 2][kk];
            float a3 = As[ty * 4 + 3][kk];
            float4 b4 = *(float4*)&Bs[kk][tx * 4];
            acc[0][0] = fmaf(a0, b4.x, acc[0][0]);
            acc[0][1] = fmaf(a0, b4.y, acc[0][1]);
            acc[0][2] = fmaf(a0, b4.z, acc[0][2]);
            acc[0][3] = fmaf(a0, b4.w, acc[0][3]);
            acc[1][0] = fmaf(a1, b4.x, acc[1][0]);
            acc[1][1] = fmaf(a1, b4.y, acc[1][1]);
            acc[1][2] = fmaf(a1, b4.z, acc[1][2]);
            acc[1][3] = fmaf(a1, b4.w, acc[1][3]);
            acc[2][0] = fmaf(a2, b4.x, acc[2][0]);
            acc[2][1] = fmaf(a2, b4.y, acc[2][1]);
            acc[2][2] = fmaf(a2, b4.z, acc[2][2]);
            acc[2][3] = fmaf(a2, b4.w, acc[2][3]);
            acc[3][0] = fmaf(a3, b4.x, acc[3][0]);
            acc[3][1] = fmaf(a3, b4.y, acc[3][1]);
            acc[3][2] = fmaf(a3, b4.z, acc[3][2]);
            acc[3][3] = fmaf(a3, b4.w, acc[3][3]);
        }
        __syncthreads();
    }

    #pragma unroll
    for (int i = 0; i < 4; i++) {
        float4 v;
        v.x = acc[i][0] * scale;
        v.y = acc[i][1] * scale;
        v.z = acc[i][2] * scale;
        v.w = acc[i][3] * scale;
        *(float4*)&out[(size_t)(m0 + ty * 4 + i) * H_ + tx * 4] = v;
    }
}

// ---------------- split-K causal flash attention -----------------------------
// grid: (S_/QB, B_, NS), block: 128 threads, one query per thread.
__global__ __launch_bounds__(128) void attn_kernel()
{
    const int b  = blockIdx.y;
    const int qb = blockIdx.x;
    const int split = blockIdx.z;
    const int qi = qb * QB + threadIdx.x;          // query index in sequence

    const int range = qb * QB + QB;                // keys 0..range-1 relevant
    const int chunk = ((range + NS * TK - 1) / (NS * TK)) * TK;
    const int k_begin = split * chunk;
    const int k_end   = min(k_begin + chunk, range);

    __shared__ float Ks[TK][H_];
    __shared__ float Vs[TK][H_];

    float q[H_], o[H_];
    float m = -1e30f, l = 0.0f;

    const float* qptr = &g_q[((size_t)b * S_ + qi) * H_];
    #pragma unroll
    for (int d = 0; d < H_; d += 4) {
        float4 v = *(const float4*)&qptr[d];
        q[d] = v.x; q[d+1] = v.y; q[d+2] = v.z; q[d+3] = v.w;
        o[d] = 0.f; o[d+1] = 0.f; o[d+2] = 0.f; o[d+3] = 0.f;
    }

    const int lj = threadIdx.x >> 4;               // 0..7
    const int lc = (threadIdx.x & 15) * 4;         // 0..60

    for (int kv0 = k_begin; kv0 < k_end; kv0 += TK) {
        // cooperative tile load
        *(float4*)&Ks[lj][lc] = *(const float4*)&g_k[((size_t)b * S_ + kv0 + lj) * H_ + lc];
        *(float4*)&Vs[lj][lc] = *(const float4*)&g_v[((size_t)b * S_ + kv0 + lj) * H_ + lc];
        __syncthreads();

        if (kv0 <= qi) {
            float s[TK];
            float tmax = -1e30f;
            #pragma unroll
            for (int jj = 0; jj < TK; jj++) {
                float acc = 0.0f;
                #pragma unroll
                for (int d = 0; d < H_; d += 4) {
                    float4 k4 = *(float4*)&Ks[jj][d];
                    acc = fmaf(q[d],   k4.x, acc);
                    acc = fmaf(q[d+1], k4.y, acc);
                    acc = fmaf(q[d+2], k4.z, acc);
                    acc = fmaf(q[d+3], k4.w, acc);
                }
                s[jj] = (kv0 + jj <= qi) ? acc : -1e30f;
                tmax = fmaxf(tmax, s[jj]);
            }
            float newm = fmaxf(m, tmax);
            float corr = __expf(m - newm);
            m = newm;
            l *= corr;
            #pragma unroll
            for (int d = 0; d < H_; d++) o[d] *= corr;

            #pragma unroll
            for (int jj = 0; jj < TK; jj++) {
                float p = __expf(s[jj] - m);
                l += p;
                #pragma unroll
                for (int d = 0; d < H_; d += 4) {
                    float4 v4 = *(float4*)&Vs[jj][d];
                    o[d]   = fmaf(p, v4.x, o[d]);
                    o[d+1] = fmaf(p, v4.y, o[d+1]);
                    o[d+2] = fmaf(p, v4.z, o[d+2]);
                    o[d+3] = fmaf(p, v4.w, o[d+3]);
                }
            }
        }
        __syncthreads();
    }

    // write partials (always, even if this split was empty)
    const size_t qg = (size_t)b * S_ + qi;
    const size_t idx = ((size_t)split * M_ + qg) * H_;
    #pragma unroll
    for (int d = 0; d < H_; d += 4) {
        float4 v; v.x = o[d]; v.y = o[d+1]; v.z = o[d+2]; v.w = o[d+3];
        *(float4*)&g_po[idx + d] = v;
    }
    g_pm[(size_t)split * M_ + qg] = m;
    g_pl[(size_t)split * M_ + qg] = l;
}

// ---------------- split combine ----------------------------------------------
// 256 threads = 4 queries x 64 dims per block
__global__ __launch_bounds__(256) void combine_kernel(float* __restrict__ out)
{
    const int qg = blockIdx.x * 4 + (threadIdx.x >> 6);   // 0..M_-1
    const int d  = threadIdx.x & 63;

    float mv[NS], lv[NS];
    float M = -1e30f;
    #pragma unroll
    for (int s = 0; s < NS; s++) {
        mv[s] = g_pm[(size_t)s * M_ + qg];
        lv[s] = g_pl[(size_t)s * M_ + qg];
        M = fmaxf(M, mv[s]);
    }
    float L = 0.0f, acc = 0.0f;
    #pragma unroll
    for (int s = 0; s < NS; s++) {
        float w = __expf(mv[s] - M);
        L += w * lv[s];
        acc += w * g_po[((size_t)s * M_ + qg) * H_ + d];
    }
    out[(size_t)qg * H_ + d] = acc / L;
}

// ---------------- launch ------------------------------------------------------
extern "C" void kernel_launch(void* const* d_in, const int* in_sizes, int n_in,
                              void* d_out, int out_size)
{
    const float* x  = (const float*)d_in[0];
    const float* Wk = (const float*)d_in[1];
    const float* Wq = (const float*)d_in[2];
    const float* Wv = (const float*)d_in[3];
    float* out = (float*)d_out;

    proj_kernel<<<dim3(M_ / 64, 3), 256>>>(x, Wk, Wq, Wv);
    attn_kernel<<<dim3(S_ / QB, B_, NS), 128>>>();
    combine_kernel<<<M_ / 4, 256>>>(out);
}

// round 6
// speedup vs baseline: 1.3964x; 1.3964x over previous
#include <cuda_runtime.h>
#include <cuda_bf16.h>
#include <cstdint>
#include <math.h>

#define B_  8
#define S_  2048
#define E_  1024
#define H_  64
#define M_  (B_ * S_)        // 16384 rows
#define NS  4                // key-range splits
#define QB  128              // queries per attention block
#define TK  8                // key tile rows

// proj tiling
#define BM 128
#define BN 64
#define BK 32

// ---------------- scratch (static device globals; no allocation) -------------
__device__ float g_k[M_ * H_];
__device__ float g_q[M_ * H_];
__device__ float g_v[M_ * H_];
__device__ float g_po[NS * M_ * H_];   // partial O (unnormalized)
__device__ float g_pm[NS * M_];        // partial running max
__device__ float g_pl[NS * M_];        // partial running sum

// ---------------- helpers -----------------------------------------------------
__device__ __forceinline__ uint32_t f2tf32(float f) {
    uint32_t r;
    asm("cvt.rna.tf32.f32 %0, %1;" : "=r"(r) : "f"(f));
    return r;
}

__device__ __forceinline__ void mma_tf32(
    float& d0, float& d1, float& d2, float& d3,
    uint32_t a0, uint32_t a1, uint32_t a2, uint32_t a3,
    uint32_t b0, uint32_t b1)
{
    asm volatile(
        "mma.sync.aligned.m16n8k8.row.col.f32.tf32.tf32.f32 "
        "{%0,%1,%2,%3}, {%4,%5,%6,%7}, {%8,%9}, {%0,%1,%2,%3};"
        : "+f"(d0), "+f"(d1), "+f"(d2), "+f"(d3)
        : "r"(a0), "r"(a1), "r"(a2), "r"(a3), "r"(b0), "r"(b1));
}

// ---------------- QKV projection via tf32 tensor cores ------------------------
// out(M x 64) = x(M x 1024) @ W(1024 x 64); grid.y selects {K,Q,V}.
// 256 threads = 8 warps: warp_m in 0..3 (32 rows each), warp_n in 0..1 (32 cols).
__global__ __launch_bounds__(256) void proj_mma_kernel(
    const float* __restrict__ x,
    const float* __restrict__ Wk,
    const float* __restrict__ Wq,
    const float* __restrict__ Wv)
{
    const float* W;
    float* out;
    float scale = 1.0f;
    if (blockIdx.y == 0)      { W = Wk; out = g_k; }
    else if (blockIdx.y == 1) { W = Wq; out = g_q; scale = 0.125f; } // 1/sqrt(64)
    else                      { W = Wv; out = g_v; }

    // padded so fragment gathers are conflict-free
    __shared__ uint32_t As[BM][36];   // uses cols [0,32)
    __shared__ uint32_t Bs[BK][68];   // uses cols [0,64)

    const int tid    = threadIdx.x;
    const int warp   = tid >> 5;
    const int lane   = tid & 31;
    const int g      = lane >> 2;      // group id 0..7
    const int tg     = lane & 3;       // thread-in-group 0..3
    const int warp_m = warp >> 1;      // 0..3
    const int warp_n = warp & 1;       // 0..1
    const int m0     = blockIdx.x * BM;

    float acc[2][4][4];
    #pragma unroll
    for (int mi = 0; mi < 2; mi++)
        #pragma unroll
        for (int ni = 0; ni < 4; ni++)
            #pragma unroll
            for (int e = 0; e < 4; e++) acc[mi][ni][e] = 0.0f;

    for (int k0 = 0; k0 < E_; k0 += BK) {
        // load A tile: 128 x 32 floats = 1024 float4, 4 per thread
        #pragma unroll
        for (int i = 0; i < 4; i++) {
            int linear = i * 256 + tid;      // float4 index
            int row  = linear >> 3;          // 8 float4 per row
            int quad = linear & 7;
            float4 v = *(const float4*)&x[(size_t)(m0 + row) * E_ + k0 + quad * 4];
            As[row][quad * 4 + 0] = f2tf32(v.x);
            As[row][quad * 4 + 1] = f2tf32(v.y);
            As[row][quad * 4 + 2] = f2tf32(v.z);
            As[row][quad * 4 + 3] = f2tf32(v.w);
        }
        // load B tile: 32 x 64 floats = 512 float4, 2 per thread
        #pragma unroll
        for (int i = 0; i < 2; i++) {
            int linear = i * 256 + tid;
            int row  = linear >> 4;          // 16 float4 per row
            int quad = linear & 15;
            float4 v = *(const float4*)&W[(size_t)(k0 + row) * H_ + quad * 4];
            Bs[row][quad * 4 + 0] = f2tf32(v.x);
            Bs[row][quad * 4 + 1] = f2tf32(v.y);
            Bs[row][quad * 4 + 2] = f2tf32(v.z);
            Bs[row][quad * 4 + 3] = f2tf32(v.w);
        }
        __syncthreads();

        #pragma unroll
        for (int kk = 0; kk < BK; kk += 8) {
            // A fragments for the two 16-row sub-tiles of this warp
            uint32_t af[2][4];
            #pragma unroll
            for (int mi = 0; mi < 2; mi++) {
                int rb = warp_m * 32 + mi * 16;
                af[mi][0] = As[rb + g][kk + tg];
                af[mi][1] = As[rb + g + 8][kk + tg];
                af[mi][2] = As[rb + g][kk + tg + 4];
                af[mi][3] = As[rb + g + 8][kk + tg + 4];
            }
            // B fragments for the four 8-col sub-tiles
            uint32_t bf[4][2];
            #pragma unroll
            for (int ni = 0; ni < 4; ni++) {
                int nb = warp_n * 32 + ni * 8 + g;
                bf[ni][0] = Bs[kk + tg][nb];
                bf[ni][1] = Bs[kk + tg + 4][nb];
            }
            #pragma unroll
            for (int mi = 0; mi < 2; mi++)
                #pragma unroll
                for (int ni = 0; ni < 4; ni++)
                    mma_tf32(acc[mi][ni][0], acc[mi][ni][1],
                             acc[mi][ni][2], acc[mi][ni][3],
                             af[mi][0], af[mi][1], af[mi][2], af[mi][3],
                             bf[ni][0], bf[ni][1]);
        }
        __syncthreads();
    }

    // epilogue: c0 {g, 2tg}, c1 {g, 2tg+1}, c2 {g+8, 2tg}, c3 {g+8, 2tg+1}
    #pragma unroll
    for (int mi = 0; mi < 2; mi++) {
        #pragma unroll
        for (int ni = 0; ni < 4; ni++) {
            int row = m0 + warp_m * 32 + mi * 16 + g;
            int col = warp_n * 32 + ni * 8 + tg * 2;
            float2 v0, v1;
            v0.x = acc[mi][ni][0] * scale;
            v0.y = acc[mi][ni][1] * scale;
            v1.x = acc[mi][ni][2] * scale;
            v1.y = acc[mi][ni][3] * scale;
            *(float2*)&out[(size_t)row * H_ + col]       = v0;
            *(float2*)&out[(size_t)(row + 8) * H_ + col] = v1;
        }
    }
}

// ---------------- split-K causal flash attention -----------------------------
// grid: (S_/QB, B_, NS), block: 128 threads, one query per thread.
__global__ __launch_bounds__(128) void attn_kernel()
{
    const int b  = blockIdx.y;
    const int qb = blockIdx.x;
    const int split = blockIdx.z;
    const int qi = qb * QB + threadIdx.x;          // query index in sequence

    const int range = qb * QB + QB;                // keys 0..range-1 relevant
    const int chunk = ((range + NS * TK - 1) / (NS * TK)) * TK;
    const int k_begin = split * chunk;
    const int k_end   = min(k_begin + chunk, range);

    __shared__ float Ks[TK][H_];
    __shared__ float Vs[TK][H_];

    float q[H_], o[H_];
    float m = -1e30f, l = 0.0f;

    const float* qptr = &g_q[((size_t)b * S_ + qi) * H_];
    #pragma unroll
    for (int d = 0; d < H_; d += 4) {
        float4 v = *(const float4*)&qptr[d];
        q[d] = v.x; q[d+1] = v.y; q[d+2] = v.z; q[d+3] = v.w;
        o[d] = 0.f; o[d+1] = 0.f; o[d+2] = 0.f; o[d+3] = 0.f;
    }

    const int lj = threadIdx.x >> 4;               // 0..7
    const int lc = (threadIdx.x & 15) * 4;         // 0..60

    for (int kv0 = k_begin; kv0 < k_end; kv0 += TK) {
        // cooperative tile load
        *(float4*)&Ks[lj][lc] = *(const float4*)&g_k[((size_t)b * S_ + kv0 + lj) * H_ + lc];
        *(float4*)&Vs[lj][lc] = *(const float4*)&g_v[((size_t)b * S_ + kv0 + lj) * H_ + lc];
        __syncthreads();

        if (kv0 <= qi) {
            float s[TK];
            float tmax = -1e30f;
            #pragma unroll
            for (int jj = 0; jj < TK; jj++) {
                float acc = 0.0f;
                #pragma unroll
                for (int d = 0; d < H_; d += 4) {
                    float4 k4 = *(float4*)&Ks[jj][d];
                    acc = fmaf(q[d],   k4.x, acc);
                    acc = fmaf(q[d+1], k4.y, acc);
                    acc = fmaf(q[d+2], k4.z, acc);
                    acc = fmaf(q[d+3], k4.w, acc);
                }
                s[jj] = (kv0 + jj <= qi) ? acc : -1e30f;
                tmax = fmaxf(tmax, s[jj]);
            }
            float newm = fmaxf(m, tmax);
            float corr = __expf(m - newm);
            m = newm;
            l *= corr;
            #pragma unroll
            for (int d = 0; d < H_; d++) o[d] *= corr;

            #pragma unroll
            for (int jj = 0; jj < TK; jj++) {
                float p = __expf(s[jj] - m);
                l += p;
                #pragma unroll
                for (int d = 0; d < H_; d += 4) {
                    float4 v4 = *(float4*)&Vs[jj][d];
                    o[d]   = fmaf(p, v4.x, o[d]);
                    o[d+1] = fmaf(p, v4.y, o[d+1]);
                    o[d+2] = fmaf(p, v4.z, o[d+2]);
                    o[d+3] = fmaf(p, v4.w, o[d+3]);
                }
            }
        }
        __syncthreads();
    }

    // write partials (always, even if this split was empty)
    const size_t qg = (size_t)b * S_ + qi;
    const size_t idx = ((size_t)split * M_ + qg) * H_;
    #pragma unroll
    for (int d = 0; d < H_; d += 4) {
        float4 v; v.x = o[d]; v.y = o[d+1]; v.z = o[d+2]; v.w = o[d+3];
        *(float4*)&g_po[idx + d] = v;
    }
    g_pm[(size_t)split * M_ + qg] = m;
    g_pl[(size_t)split * M_ + qg] = l;
}

// ---------------- split combine ----------------------------------------------
// 256 threads = 4 queries x 64 dims per block
__global__ __launch_bounds__(256) void combine_kernel(float* __restrict__ out)
{
    const int qg = blockIdx.x * 4 + (threadIdx.x >> 6);   // 0..M_-1
    const int d  = threadIdx.x & 63;

    float mv[NS], lv[NS];
    float M = -1e30f;
    #pragma unroll
    for (int s = 0; s < NS; s++) {
        mv[s] = g_pm[(size_t)s * M_ + qg];
        lv[s] = g_pl[(size_t)s * M_ + qg];
        M = fmaxf(M, mv[s]);
    }
    float L = 0.0f, acc = 0.0f;
    #pragma unroll
    for (int s = 0; s < NS; s++) {
        float w = __expf(mv[s] - M);
        L += w * lv[s];
        acc += w * g_po[((size_t)s * M_ + qg) * H_ + d];
    }
    out[(size_t)qg * H_ + d] = acc / L;
}

// ---------------- launch ------------------------------------------------------
extern "C" void kernel_launch(void* const* d_in, const int* in_sizes, int n_in,
                              void* d_out, int out_size)
{
    const float* x  = (const float*)d_in[0];
    const float* Wk = (const float*)d_in[1];
    const float* Wq = (const float*)d_in[2];
    const float* Wv = (const float*)d_in[3];
    float* out = (float*)d_out;

    proj_mma_kernel<<<dim3(M_ / BM, 3), 256>>>(x, Wk, Wq, Wv);
    attn_kernel<<<dim3(S_ / QB, B_, NS), 128>>>();
    combine_kernel<<<M_ / 4, 256>>>(out);
}

// round 9
// speedup vs baseline: 3.1739x; 2.2729x over previous
#include <cuda_runtime.h>
#include <cuda_bf16.h>
#include <cstdint>
#include <math.h>

#define B_  8
#define S_  2048
#define E_  1024
#define H_  64
#define M_  (B_ * S_)        // 16384 rows
#define NS  4                // key-range splits
#define QB2 64               // queries per attention CTA
#define KT  64               // key tile

// proj tiling
#define BM 128
#define BK 32

// ---------------- scratch (static device globals; no allocation) -------------
__device__ float g_k[M_ * H_];
__device__ float g_q[M_ * H_];
__device__ float g_v[M_ * H_];
__device__ float g_po[NS * M_ * H_];   // partial O (unnormalized)
__device__ float g_pm[NS * M_];        // partial running max
__device__ float g_pl[NS * M_];        // partial running sum

// ---------------- helpers -----------------------------------------------------
__device__ __forceinline__ uint32_t f2tf32(float f) {
    uint32_t r;
    asm("cvt.rna.tf32.f32 %0, %1;" : "=r"(r) : "f"(f));
    return r;
}

__device__ __forceinline__ void mma_tf32(
    float& d0, float& d1, float& d2, float& d3,
    uint32_t a0, uint32_t a1, uint32_t a2, uint32_t a3,
    uint32_t b0, uint32_t b1)
{
    asm volatile(
        "mma.sync.aligned.m16n8k8.row.col.f32.tf32.tf32.f32 "
        "{%0,%1,%2,%3}, {%4,%5,%6,%7}, {%8,%9}, {%0,%1,%2,%3};"
        : "+f"(d0), "+f"(d1), "+f"(d2), "+f"(d3)
        : "r"(a0), "r"(a1), "r"(a2), "r"(a3), "r"(b0), "r"(b1));
}

// ---------------- QKV projection via tf32 tensor cores ------------------------
__global__ __launch_bounds__(256) void proj_mma_kernel(
    const float* __restrict__ x,
    const float* __restrict__ Wk,
    const float* __restrict__ Wq,
    const float* __restrict__ Wv)
{
    const float* W;
    float* out;
    float scale = 1.0f;
    if (blockIdx.y == 0)      { W = Wk; out = g_k; }
    else if (blockIdx.y == 1) { W = Wq; out = g_q; scale = 0.125f; }
    else                      { W = Wv; out = g_v; }

    __shared__ uint32_t As[BM][36];
    __shared__ uint32_t Bs[BK][68];

    const int tid    = threadIdx.x;
    const int warp   = tid >> 5;
    const int lane   = tid & 31;
    const int g      = lane >> 2;
    const int tg     = lane & 3;
    const int warp_m = warp >> 1;
    const int warp_n = warp & 1;
    const int m0     = blockIdx.x * BM;

    float acc[2][4][4];
    #pragma unroll
    for (int mi = 0; mi < 2; mi++)
        #pragma unroll
        for (int ni = 0; ni < 4; ni++)
            #pragma unroll
            for (int e = 0; e < 4; e++) acc[mi][ni][e] = 0.0f;

    for (int k0 = 0; k0 < E_; k0 += BK) {
        #pragma unroll
        for (int i = 0; i < 4; i++) {
            int linear = i * 256 + tid;
            int row  = linear >> 3;
            int quad = linear & 7;
            float4 v = *(const float4*)&x[(size_t)(m0 + row) * E_ + k0 + quad * 4];
            As[row][quad * 4 + 0] = f2tf32(v.x);
            As[row][quad * 4 + 1] = f2tf32(v.y);
            As[row][quad * 4 + 2] = f2tf32(v.z);
            As[row][quad * 4 + 3] = f2tf32(v.w);
        }
        #pragma unroll
        for (int i = 0; i < 2; i++) {
            int linear = i * 256 + tid;
            int row  = linear >> 4;
            int quad = linear & 15;
            float4 v = *(const float4*)&W[(size_t)(k0 + row) * H_ + quad * 4];
            Bs[row][quad * 4 + 0] = f2tf32(v.x);
            Bs[row][quad * 4 + 1] = f2tf32(v.y);
            Bs[row][quad * 4 + 2] = f2tf32(v.z);
            Bs[row][quad * 4 + 3] = f2tf32(v.w);
        }
        __syncthreads();

        #pragma unroll
        for (int kk = 0; kk < BK; kk += 8) {
            uint32_t af[2][4];
            #pragma unroll
            for (int mi = 0; mi < 2; mi++) {
                int rb = warp_m * 32 + mi * 16;
                af[mi][0] = As[rb + g][kk + tg];
                af[mi][1] = As[rb + g + 8][kk + tg];
                af[mi][2] = As[rb + g][kk + tg + 4];
                af[mi][3] = As[rb + g + 8][kk + tg + 4];
            }
            uint32_t bf[4][2];
            #pragma unroll
            for (int ni = 0; ni < 4; ni++) {
                int nb = warp_n * 32 + ni * 8 + g;
                bf[ni][0] = Bs[kk + tg][nb];
                bf[ni][1] = Bs[kk + tg + 4][nb];
            }
            #pragma unroll
            for (int mi = 0; mi < 2; mi++)
                #pragma unroll
                for (int ni = 0; ni < 4; ni++)
                    mma_tf32(acc[mi][ni][0], acc[mi][ni][1],
                             acc[mi][ni][2], acc[mi][ni][3],
                             af[mi][0], af[mi][1], af[mi][2], af[mi][3],
                             bf[ni][0], bf[ni][1]);
        }
        __syncthreads();
    }

    #pragma unroll
    for (int mi = 0; mi < 2; mi++) {
        #pragma unroll
        for (int ni = 0; ni < 4; ni++) {
            int row = m0 + warp_m * 32 + mi * 16 + g;
            int col = warp_n * 32 + ni * 8 + tg * 2;
            float2 v0, v1;
            v0.x = acc[mi][ni][0] * scale;
            v0.y = acc[mi][ni][1] * scale;
            v1.x = acc[mi][ni][2] * scale;
            v1.y = acc[mi][ni][3] * scale;
            *(float2*)&out[(size_t)row * H_ + col]       = v0;
            *(float2*)&out[(size_t)(row + 8) * H_ + col] = v1;
        }
    }
}

// ---------------- tf32 MMA split-K causal flash attention ---------------------
// grid: (S_/QB2, B_, NS), 128 threads = 4 warps, each warp owns 16 query rows.
__global__ __launch_bounds__(128) void attn_mma_kernel()
{
    const int b     = blockIdx.y;
    const int qb    = blockIdx.x;
    const int split = blockIdx.z;
    const int q0    = qb * QB2;

    const int range   = q0 + QB2;                     // keys 0..range-1
    const int chunk   = ((range + NS * KT - 1) / (NS * KT)) * KT;
    const int k_begin = split * chunk;
    const int k_end   = min(k_begin + chunk, range);

    // KPs: K tile during QK, P tile during PV (aliased). stride 68 -> 4g+tg banks
    __shared__ uint32_t KPs[KT][68];
    // Vs: stride 72 -> 8tg+g banks for B-fragment gathers
    __shared__ uint32_t Vs[KT][72];

    const int tid  = threadIdx.x;
    const int warp = tid >> 5;
    const int lane = tid & 31;
    const int g    = lane >> 2;
    const int tg   = lane & 3;
    const int wr   = warp * 16;                        // warp row base (local)

    // ---- stage Q tile into KPs, pull fragments to registers ----
    #pragma unroll
    for (int i = 0; i < 8; i++) {
        int idx  = i * 128 + tid;                      // float4 index
        int row  = idx >> 4;
        int quad = idx & 15;
        float4 v = *(const float4*)&g_q[((size_t)b * S_ + q0 + row) * H_ + quad * 4];
        KPs[row][quad * 4 + 0] = f2tf32(v.x);
        KPs[row][quad * 4 + 1] = f2tf32(v.y);
        KPs[row][quad * 4 + 2] = f2tf32(v.z);
        KPs[row][quad * 4 + 3] = f2tf32(v.w);
    }
    __syncthreads();
    uint32_t qf[8][4];
    #pragma unroll
    for (int kk = 0; kk < 8; kk++) {
        qf[kk][0] = KPs[wr + g][kk * 8 + tg];
        qf[kk][1] = KPs[wr + g + 8][kk * 8 + tg];
        qf[kk][2] = KPs[wr + g][kk * 8 + tg + 4];
        qf[kk][3] = KPs[wr + g + 8][kk * 8 + tg + 4];
    }
    __syncthreads();

    float oacc[8][4];
    #pragma unroll
    for (int nt = 0; nt < 8; nt++)
        #pragma unroll
        for (int e = 0; e < 4; e++) oacc[nt][e] = 0.0f;
    float m0r = -1e30f, l0 = 0.0f;
    float m1r = -1e30f, l1 = 0.0f;

    for (int kb = k_begin; kb < k_end; kb += KT) {
        // ---- load K, V tiles ----
        #pragma unroll
        for (int i = 0; i < 8; i++) {
            int idx  = i * 128 + tid;
            int row  = idx >> 4;
            int quad = idx & 15;
            size_t base = ((size_t)b * S_ + kb + row) * H_ + quad * 4;
            float4 kv = *(const float4*)&g_k[base];
            KPs[row][quad * 4 + 0] = f2tf32(kv.x);
            KPs[row][quad * 4 + 1] = f2tf32(kv.y);
            KPs[row][quad * 4 + 2] = f2tf32(kv.z);
            KPs[row][quad * 4 + 3] = f2tf32(kv.w);
            float4 vv = *(const float4*)&g_v[base];
            Vs[row][quad * 4 + 0] = f2tf32(vv.x);
            Vs[row][quad * 4 + 1] = f2tf32(vv.y);
            Vs[row][quad * 4 + 2] = f2tf32(vv.z);
            Vs[row][quad * 4 + 3] = f2tf32(vv.w);
        }
        __syncthreads();

        // ---- S = Q @ K^T ----
        float sacc[8][4];
        #pragma unroll
        for (int nt = 0; nt < 8; nt++)
            #pragma unroll
            for (int e = 0; e < 4; e++) sacc[nt][e] = 0.0f;

        #pragma unroll
        for (int kk = 0; kk < 8; kk++) {
            #pragma unroll
            for (int nt = 0; nt < 8; nt++) {
                uint32_t b0 = KPs[nt * 8 + g][kk * 8 + tg];
                uint32_t b1 = KPs[nt * 8 + g][kk * 8 + tg + 4];
                mma_tf32(sacc[nt][0], sacc[nt][1], sacc[nt][2], sacc[nt][3],
                         qf[kk][0], qf[kk][1], qf[kk][2], qf[kk][3], b0, b1);
            }
        }

        // ---- causal mask (only diagonal tile) ----
        if (kb == q0) {
            const int r0g = q0 + wr + g;
            const int r1g = r0g + 8;
            #pragma unroll
            for (int nt = 0; nt < 8; nt++) {
                int key = kb + nt * 8 + 2 * tg;
                if (key     > r0g) sacc[nt][0] = -1e30f;
                if (key + 1 > r0g) sacc[nt][1] = -1e30f;
                if (key     > r1g) sacc[nt][2] = -1e30f;
                if (key + 1 > r1g) sacc[nt][3] = -1e30f;
            }
        }

        // ---- online softmax ----
        float tmax0 = -1e30f, tmax1 = -1e30f;
        #pragma unroll
        for (int nt = 0; nt < 8; nt++) {
            tmax0 = fmaxf(tmax0, fmaxf(sacc[nt][0], sacc[nt][1]));
            tmax1 = fmaxf(tmax1, fmaxf(sacc[nt][2], sacc[nt][3]));
        }
        tmax0 = fmaxf(tmax0, __shfl_xor_sync(0xffffffffu, tmax0, 1));
        tmax0 = fmaxf(tmax0, __shfl_xor_sync(0xffffffffu, tmax0, 2));
        tmax1 = fmaxf(tmax1, __shfl_xor_sync(0xffffffffu, tmax1, 1));
        tmax1 = fmaxf(tmax1, __shfl_xor_sync(0xffffffffu, tmax1, 2));

        float ms_old0 = fmaxf(m0r, -1e20f);
        float ms_old1 = fmaxf(m1r, -1e20f);
        m0r = fmaxf(m0r, tmax0);
        m1r = fmaxf(m1r, tmax1);
        float ms0 = fmaxf(m0r, -1e20f);
        float ms1 = fmaxf(m1r, -1e20f);
        float corr0 = __expf(ms_old0 - ms0);
        float corr1 = __expf(ms_old1 - ms1);

        float rsum0 = 0.0f, rsum1 = 0.0f;
        float p[8][4];
        #pragma unroll
        for (int nt = 0; nt < 8; nt++) {
            p[nt][0] = __expf(sacc[nt][0] - ms0);
            p[nt][1] = __expf(sacc[nt][1] - ms0);
            p[nt][2] = __expf(sacc[nt][2] - ms1);
            p[nt][3] = __expf(sacc[nt][3] - ms1);
            rsum0 += p[nt][0] + p[nt][1];
            rsum1 += p[nt][2] + p[nt][3];
        }
        rsum0 += __shfl_xor_sync(0xffffffffu, rsum0, 1);
        rsum0 += __shfl_xor_sync(0xffffffffu, rsum0, 2);
        rsum1 += __shfl_xor_sync(0xffffffffu, rsum1, 1);
        rsum1 += __shfl_xor_sync(0xffffffffu, rsum1, 2);
        l0 = l0 * corr0 + rsum0;
        l1 = l1 * corr1 + rsum1;
        #pragma unroll
        for (int nt = 0; nt < 8; nt++) {
            oacc[nt][0] *= corr0;
            oacc[nt][1] *= corr0;
            oacc[nt][2] *= corr1;
            oacc[nt][3] *= corr1;
        }

        // ---- write P into KPs (aliased; all warps must be done reading K) ----
        __syncthreads();
        #pragma unroll
        for (int nt = 0; nt < 8; nt++) {
            KPs[wr + g][nt * 8 + 2 * tg]         = f2tf32(p[nt][0]);
            KPs[wr + g][nt * 8 + 2 * tg + 1]     = f2tf32(p[nt][1]);
            KPs[wr + g + 8][nt * 8 + 2 * tg]     = f2tf32(p[nt][2]);
            KPs[wr + g + 8][nt * 8 + 2 * tg + 1] = f2tf32(p[nt][3]);
        }
        __syncwarp();

        // ---- O += P @ V ----
        #pragma unroll
        for (int kk = 0; kk < 8; kk++) {
            uint32_t pf0 = KPs[wr + g][kk * 8 + tg];
            uint32_t pf1 = KPs[wr + g + 8][kk * 8 + tg];
            uint32_t pf2 = KPs[wr + g][kk * 8 + tg + 4];
            uint32_t pf3 = KPs[wr + g + 8][kk * 8 + tg + 4];
            #pragma unroll
            for (int nt = 0; nt < 8; nt++) {
                uint32_t b0 = Vs[kk * 8 + tg][nt * 8 + g];
                uint32_t b1 = Vs[kk * 8 + tg + 4][nt * 8 + g];
                mma_tf32(oacc[nt][0], oacc[nt][1], oacc[nt][2], oacc[nt][3],
                         pf0, pf1, pf2, pf3, b0, b1);
            }
        }
        __syncthreads();   // protect KPs/Vs before next tile load
    }

    // ---- write partials ----
    const int r0 = q0 + wr + g;
    const int r1 = r0 + 8;
    const size_t row0 = (size_t)b * S_ + r0;
    const size_t row1 = (size_t)b * S_ + r1;
    #pragma unroll
    for (int nt = 0; nt < 8; nt++) {
        float2 v0; v0.x = oacc[nt][0]; v0.y = oacc[nt][1];
        float2 v1; v1.x = oacc[nt][2]; v1.y = oacc[nt][3];
        *(float2*)&g_po[((size_t)split * M_ + row0) * H_ + nt * 8 + 2 * tg] = v0;
        *(float2*)&g_po[((size_t)split * M_ + row1) * H_ + nt * 8 + 2 * tg] = v1;
    }
    if (tg == 0) {
        g_pm[(size_t)split * M_ + row0] = m0r;
        g_pl[(size_t)split * M_ + row0] = l0;
        g_pm[(size_t)split * M_ + row1] = m1r;
        g_pl[(size_t)split * M_ + row1] = l1;
    }
}

// ---------------- split combine ----------------------------------------------
__global__ __launch_bounds__(256) void combine_kernel(float* __restrict__ out)
{
    const int qg = blockIdx.x * 4 + (threadIdx.x >> 6);
    const int d  = threadIdx.x & 63;

    float mv[NS], lv[NS];
    float M = -1e30f;
    #pragma unroll
    for (int s = 0; s < NS; s++) {
        mv[s] = g_pm[(size_t)s * M_ + qg];
        lv[s] = g_pl[(size_t)s * M_ + qg];
        M = fmaxf(M, mv[s]);
    }
    float L = 0.0f, acc = 0.0f;
    #pragma unroll
    for (int s = 0; s < NS; s++) {
        float w = __expf(mv[s] - M);
        L += w * lv[s];
        acc += w * g_po[((size_t)s * M_ + qg) * H_ + d];
    }
    out[(size_t)qg * H_ + d] = acc / L;
}

// ---------------- launch ------------------------------------------------------
extern "C" void kernel_launch(void* const* d_in, const int* in_sizes, int n_in,
                              void* d_out, int out_size)
{
    const float* x  = (const float*)d_in[0];
    const float* Wk = (const float*)d_in[1];
    const float* Wq = (const float*)d_in[2];
    const float* Wv = (const float*)d_in[3];
    float* out = (float*)d_out;

    proj_mma_kernel<<<dim3(M_ / BM, 3), 256>>>(x, Wk, Wq, Wv);
    attn_mma_kernel<<<dim3(S_ / QB2, B_, NS), 128>>>();
    combine_kernel<<<M_ / 4, 256>>>(out);
}

// round 11
// speedup vs baseline: 3.5027x; 1.1036x over previous
#include <cuda_runtime.h>
#include <cuda_bf16.h>
#include <cstdint>
#include <math.h>

#define B_  8
#define S_  2048
#define E_  1024
#define H_  64
#define M_  (B_ * S_)        // 16384 rows
#define NS  4                // key-range splits
#define QB2 64               // queries per attention CTA
#define KT  64               // key tile

// proj tiling
#define BM 128
#define BK 32

// ---------------- scratch (static device globals; no allocation) -------------
__device__ float g_k[M_ * H_];
__device__ float g_q[M_ * H_];
__device__ float g_v[M_ * H_];
__device__ float g_po[NS * M_ * H_];   // partial O (unnormalized)
__device__ float g_pm[NS * M_];        // partial running max
__device__ float g_pl[NS * M_];        // partial running sum

// ---------------- helpers -----------------------------------------------------
__device__ __forceinline__ uint32_t f2tf32(float f) {
    uint32_t r;
    asm("cvt.rna.tf32.f32 %0, %1;" : "=r"(r) : "f"(f));
    return r;
}

__device__ __forceinline__ void mma_tf32(
    float& d0, float& d1, float& d2, float& d3,
    uint32_t a0, uint32_t a1, uint32_t a2, uint32_t a3,
    uint32_t b0, uint32_t b1)
{
    asm volatile(
        "mma.sync.aligned.m16n8k8.row.col.f32.tf32.tf32.f32 "
        "{%0,%1,%2,%3}, {%4,%5,%6,%7}, {%8,%9}, {%0,%1,%2,%3};"
        : "+f"(d0), "+f"(d1), "+f"(d2), "+f"(d3)
        : "r"(a0), "r"(a1), "r"(a2), "r"(a3), "r"(b0), "r"(b1));
}

// ---------------- FUSED QKV projection (one pass over x) ----------------------
// K/Q/V = x(M x 1024) @ {Wk,Wq,Wv}(1024 x 64), one block per 128 rows.
// 8 warps: warp_m 0..3 (32 rows), warp_n 0..1 (32 cols). A fragments reused 3x.
// Register-prefetch of next k-tile overlaps LDG latency with MMA compute.
__global__ __launch_bounds__(256) void proj_fused_kernel(
    const float* __restrict__ x,
    const float* __restrict__ Wk,
    const float* __restrict__ Wq,
    const float* __restrict__ Wv)
{
    __shared__ uint32_t As[BM][36];        // x tile (tf32), padded
    __shared__ uint32_t Bs[3][BK][68];     // Wk/Wq/Wv tiles (tf32), padded

    const int tid    = threadIdx.x;
    const int warp   = tid >> 5;
    const int lane   = tid & 31;
    const int g      = lane >> 2;
    const int tg     = lane & 3;
    const int warp_m = warp >> 1;
    const int warp_n = warp & 1;
    const int m0     = blockIdx.x * BM;

    const float* Wp[3] = { Wk, Wq, Wv };

    float acc[3][2][4][4];
    #pragma unroll
    for (int p = 0; p < 3; p++)
        #pragma unroll
        for (int mi = 0; mi < 2; mi++)
            #pragma unroll
            for (int ni = 0; ni < 4; ni++)
                #pragma unroll
                for (int e = 0; e < 4; e++) acc[p][mi][ni][e] = 0.0f;

    // A-tile load geometry: 1024 float4, 4 per thread
    const int a_row[4]  = { (0*256+tid) >> 3, (1*256+tid) >> 3,
                            (2*256+tid) >> 3, (3*256+tid) >> 3 };
    const int a_quad    = tid & 7;
    // B-tile load geometry: 512 float4, 2 per thread
    const int b_row[2]  = { (0*256+tid) >> 4, (1*256+tid) >> 4 };
    const int b_quad    = tid & 15;

    // ---- prologue prefetch (k0 = 0) ----
    float4 xa[4];
    float4 wb[3][2];
    #pragma unroll
    for (int i = 0; i < 4; i++)
        xa[i] = *(const float4*)&x[(size_t)(m0 + a_row[i]) * E_ + a_quad * 4];
    #pragma unroll
    for (int p = 0; p < 3; p++)
        #pragma unroll
        for (int i = 0; i < 2; i++)
            wb[p][i] = *(const float4*)&Wp[p][(size_t)b_row[i] * H_ + b_quad * 4];

    for (int k0 = 0; k0 < E_; k0 += BK) {
        // ---- stage prefetched regs into smem (convert to tf32) ----
        #pragma unroll
        for (int i = 0; i < 4; i++) {
            As[a_row[i]][a_quad * 4 + 0] = f2tf32(xa[i].x);
            As[a_row[i]][a_quad * 4 + 1] = f2tf32(xa[i].y);
            As[a_row[i]][a_quad * 4 + 2] = f2tf32(xa[i].z);
            As[a_row[i]][a_quad * 4 + 3] = f2tf32(xa[i].w);
        }
        #pragma unroll
        for (int p = 0; p < 3; p++)
            #pragma unroll
            for (int i = 0; i < 2; i++) {
                Bs[p][b_row[i]][b_quad * 4 + 0] = f2tf32(wb[p][i].x);
                Bs[p][b_row[i]][b_quad * 4 + 1] = f2tf32(wb[p][i].y);
                Bs[p][b_row[i]][b_quad * 4 + 2] = f2tf32(wb[p][i].z);
                Bs[p][b_row[i]][b_quad * 4 + 3] = f2tf32(wb[p][i].w);
            }
        __syncthreads();

        // ---- prefetch next tile (LDG overlaps with MMAs below) ----
        if (k0 + BK < E_) {
            const int kn = k0 + BK;
            #pragma unroll
            for (int i = 0; i < 4; i++)
                xa[i] = *(const float4*)&x[(size_t)(m0 + a_row[i]) * E_ + kn + a_quad * 4];
            #pragma unroll
            for (int p = 0; p < 3; p++)
                #pragma unroll
                for (int i = 0; i < 2; i++)
                    wb[p][i] = *(const float4*)&Wp[p][(size_t)(kn + b_row[i]) * H_ + b_quad * 4];
        }

        // ---- compute: A fragments loaded once, fed to all 3 projections ----
        #pragma unroll
        for (int kk = 0; kk < BK; kk += 8) {
            uint32_t af[2][4];
            #pragma unroll
            for (int mi = 0; mi < 2; mi++) {
                int rb = warp_m * 32 + mi * 16;
                af[mi][0] = As[rb + g][kk + tg];
                af[mi][1] = As[rb + g + 8][kk + tg];
                af[mi][2] = As[rb + g][kk + tg + 4];
                af[mi][3] = As[rb + g + 8][kk + tg + 4];
            }
            #pragma unroll
            for (int p = 0; p < 3; p++) {
                uint32_t bf[4][2];
                #pragma unroll
                for (int ni = 0; ni < 4; ni++) {
                    int nb = warp_n * 32 + ni * 8 + g;
                    bf[ni][0] = Bs[p][kk + tg][nb];
                    bf[ni][1] = Bs[p][kk + tg + 4][nb];
                }
                #pragma unroll
                for (int mi = 0; mi < 2; mi++)
                    #pragma unroll
                    for (int ni = 0; ni < 4; ni++)
                        mma_tf32(acc[p][mi][ni][0], acc[p][mi][ni][1],
                                 acc[p][mi][ni][2], acc[p][mi][ni][3],
                                 af[mi][0], af[mi][1], af[mi][2], af[mi][3],
                                 bf[ni][0], bf[ni][1]);
            }
        }
        __syncthreads();
    }

    // ---- epilogue: write K, Q (scaled), V ----
    float* outp[3] = { g_k, g_q, g_v };
    #pragma unroll
    for (int p = 0; p < 3; p++) {
        const float scale = (p == 1) ? 0.125f : 1.0f;   // q pre-scaled by H^-0.5
        #pragma unroll
        for (int mi = 0; mi < 2; mi++) {
            #pragma unroll
            for (int ni = 0; ni < 4; ni++) {
                int row = m0 + warp_m * 32 + mi * 16 + g;
                int col = warp_n * 32 + ni * 8 + tg * 2;
                float2 v0, v1;
                v0.x = acc[p][mi][ni][0] * scale;
                v0.y = acc[p][mi][ni][1] * scale;
                v1.x = acc[p][mi][ni][2] * scale;
                v1.y = acc[p][mi][ni][3] * scale;
                *(float2*)&outp[p][(size_t)row * H_ + col]       = v0;
                *(float2*)&outp[p][(size_t)(row + 8) * H_ + col] = v1;
            }
        }
    }
}

// ---------------- tf32 MMA split-K causal flash attention ---------------------
// grid: (S_/QB2, B_, NS), 128 threads = 4 warps, each warp owns 16 query rows.
__global__ __launch_bounds__(128) void attn_mma_kernel()
{
    const int b     = blockIdx.y;
    const int qb    = blockIdx.x;
    const int split = blockIdx.z;
    const int q0    = qb * QB2;

    const int range   = q0 + QB2;                     // keys 0..range-1
    const int chunk   = ((range + NS * KT - 1) / (NS * KT)) * KT;
    const int k_begin = split * chunk;
    const int k_end   = min(k_begin + chunk, range);

    // KPs: K tile during QK, P tile during PV (aliased). stride 68 -> 4g+tg banks
    __shared__ uint32_t KPs[KT][68];
    // Vs: stride 72 -> 8tg+g banks for B-fragment gathers
    __shared__ uint32_t Vs[KT][72];

    const int tid  = threadIdx.x;
    const int warp = tid >> 5;
    const int lane = tid & 31;
    const int g    = lane >> 2;
    const int tg   = lane & 3;
    const int wr   = warp * 16;                        // warp row base (local)

    // ---- stage Q tile into KPs, pull fragments to registers ----
    #pragma unroll
    for (int i = 0; i < 8; i++) {
        int idx  = i * 128 + tid;                      // float4 index
        int row  = idx >> 4;
        int quad = idx & 15;
        float4 v = *(const float4*)&g_q[((size_t)b * S_ + q0 + row) * H_ + quad * 4];
        KPs[row][quad * 4 + 0] = f2tf32(v.x);
        KPs[row][quad * 4 + 1] = f2tf32(v.y);
        KPs[row][quad * 4 + 2] = f2tf32(v.z);
        KPs[row][quad * 4 + 3] = f2tf32(v.w);
    }
    __syncthreads();
    uint32_t qf[8][4];
    #pragma unroll
    for (int kk = 0; kk < 8; kk++) {
        qf[kk][0] = KPs[wr + g][kk * 8 + tg];
        qf[kk][1] = KPs[wr + g + 8][kk * 8 + tg];
        qf[kk][2] = KPs[wr + g][kk * 8 + tg + 4];
        qf[kk][3] = KPs[wr + g + 8][kk * 8 + tg + 4];
    }
    __syncthreads();

    float oacc[8][4];
    #pragma unroll
    for (int nt = 0; nt < 8; nt++)
        #pragma unroll
        for (int e = 0; e < 4; e++) oacc[nt][e] = 0.0f;
    float m0r = -1e30f, l0 = 0.0f;
    float m1r = -1e30f, l1 = 0.0f;

    for (int kb = k_begin; kb < k_end; kb += KT) {
        // ---- load K, V tiles ----
        #pragma unroll
        for (int i = 0; i < 8; i++) {
            int idx  = i * 128 + tid;
            int row  = idx >> 4;
            int quad = idx & 15;
            size_t base = ((size_t)b * S_ + kb + row) * H_ + quad * 4;
            float4 kv = *(const float4*)&g_k[base];
            KPs[row][quad * 4 + 0] = f2tf32(kv.x);
            KPs[row][quad * 4 + 1] = f2tf32(kv.y);
            KPs[row][quad * 4 + 2] = f2tf32(kv.z);
            KPs[row][quad * 4 + 3] = f2tf32(kv.w);
            float4 vv = *(const float4*)&g_v[base];
            Vs[row][quad * 4 + 0] = f2tf32(vv.x);
            Vs[row][quad * 4 + 1] = f2tf32(vv.y);
            Vs[row][quad * 4 + 2] = f2tf32(vv.z);
            Vs[row][quad * 4 + 3] = f2tf32(vv.w);
        }
        __syncthreads();

        // ---- S = Q @ K^T ----
        float sacc[8][4];
        #pragma unroll
        for (int nt = 0; nt < 8; nt++)
            #pragma unroll
            for (int e = 0; e < 4; e++) sacc[nt][e] = 0.0f;

        #pragma unroll
        for (int kk = 0; kk < 8; kk++) {
            #pragma unroll
            for (int nt = 0; nt < 8; nt++) {
                uint32_t b0 = KPs[nt * 8 + g][kk * 8 + tg];
                uint32_t b1 = KPs[nt * 8 + g][kk * 8 + tg + 4];
                mma_tf32(sacc[nt][0], sacc[nt][1], sacc[nt][2], sacc[nt][3],
                         qf[kk][0], qf[kk][1], qf[kk][2], qf[kk][3], b0, b1);
            }
        }

        // ---- causal mask (only diagonal tile) ----
        if (kb == q0) {
            const int r0g = q0 + wr + g;
            const int r1g = r0g + 8;
            #pragma unroll
            for (int nt = 0; nt < 8; nt++) {
                int key = kb + nt * 8 + 2 * tg;
                if (key     > r0g) sacc[nt][0] = -1e30f;
                if (key + 1 > r0g) sacc[nt][1] = -1e30f;
                if (key     > r1g) sacc[nt][2] = -1e30f;
                if (key + 1 > r1g) sacc[nt][3] = -1e30f;
            }
        }

        // ---- online softmax ----
        float tmax0 = -1e30f, tmax1 = -1e30f;
        #pragma unroll
        for (int nt = 0; nt < 8; nt++) {
            tmax0 = fmaxf(tmax0, fmaxf(sacc[nt][0], sacc[nt][1]));
            tmax1 = fmaxf(tmax1, fmaxf(sacc[nt][2], sacc[nt][3]));
        }
        tmax0 = fmaxf(tmax0, __shfl_xor_sync(0xffffffffu, tmax0, 1));
        tmax0 = fmaxf(tmax0, __shfl_xor_sync(0xffffffffu, tmax0, 2));
        tmax1 = fmaxf(tmax1, __shfl_xor_sync(0xffffffffu, tmax1, 1));
        tmax1 = fmaxf(tmax1, __shfl_xor_sync(0xffffffffu, tmax1, 2));

        float ms_old0 = fmaxf(m0r, -1e20f);
        float ms_old1 = fmaxf(m1r, -1e20f);
        m0r = fmaxf(m0r, tmax0);
        m1r = fmaxf(m1r, tmax1);
        float ms0 = fmaxf(m0r, -1e20f);
        float ms1 = fmaxf(m1r, -1e20f);
        float corr0 = __expf(ms_old0 - ms0);
        float corr1 = __expf(ms_old1 - ms1);

        float rsum0 = 0.0f, rsum1 = 0.0f;
        float p[8][4];
        #pragma unroll
        for (int nt = 0; nt < 8; nt++) {
            p[nt][0] = __expf(sacc[nt][0] - ms0);
            p[nt][1] = __expf(sacc[nt][1] - ms0);
            p[nt][2] = __expf(sacc[nt][2] - ms1);
            p[nt][3] = __expf(sacc[nt][3] - ms1);
            rsum0 += p[nt][0] + p[nt][1];
            rsum1 += p[nt][2] + p[nt][3];
        }
        rsum0 += __shfl_xor_sync(0xffffffffu, rsum0, 1);
        rsum0 += __shfl_xor_sync(0xffffffffu, rsum0, 2);
        rsum1 += __shfl_xor_sync(0xffffffffu, rsum1, 1);
        rsum1 += __shfl_xor_sync(0xffffffffu, rsum1, 2);
        l0 = l0 * corr0 + rsum0;
        l1 = l1 * corr1 + rsum1;
        #pragma unroll
        for (int nt = 0; nt < 8; nt++) {
            oacc[nt][0] *= corr0;
            oacc[nt][1] *= corr0;
            oacc[nt][2] *= corr1;
            oacc[nt][3] *= corr1;
        }

        // ---- write P into KPs (aliased; all warps must be done reading K) ----
        __syncthreads();
        #pragma unroll
        for (int nt = 0; nt < 8; nt++) {
            KPs[wr + g][nt * 8 + 2 * tg]         = f2tf32(p[nt][0]);
            KPs[wr + g][nt * 8 + 2 * tg + 1]     = f2tf32(p[nt][1]);
            KPs[wr + g + 8][nt * 8 + 2 * tg]     = f2tf32(p[nt][2]);
            KPs[wr + g + 8][nt * 8 + 2 * tg + 1] = f2tf32(p[nt][3]);
        }
        __syncwarp();

        // ---- O += P @ V ----
        #pragma unroll
        for (int kk = 0; kk < 8; kk++) {
            uint32_t pf0 = KPs[wr + g][kk * 8 + tg];
            uint32_t pf1 = KPs[wr + g + 8][kk * 8 + tg];
            uint32_t pf2 = KPs[wr + g][kk * 8 + tg + 4];
            uint32_t pf3 = KPs[wr + g + 8][kk * 8 + tg + 4];
            #pragma unroll
            for (int nt = 0; nt < 8; nt++) {
                uint32_t b0 = Vs[kk * 8 + tg][nt * 8 + g];
                uint32_t b1 = Vs[kk * 8 + tg + 4][nt * 8 + g];
                mma_tf32(oacc[nt][0], oacc[nt][1], oacc[nt][2], oacc[nt][3],
                         pf0, pf1, pf2, pf3, b0, b1);
            }
        }
        __syncthreads();   // protect KPs/Vs before next tile load
    }

    // ---- write partials ----
    const int r0 = q0 + wr + g;
    const int r1 = r0 + 8;
    const size_t row0 = (size_t)b * S_ + r0;
    const size_t row1 = (size_t)b * S_ + r1;
    #pragma unroll
    for (int nt = 0; nt < 8; nt++) {
        float2 v0; v0.x = oacc[nt][0]; v0.y = oacc[nt][1];
        float2 v1; v1.x = oacc[nt][2]; v1.y = oacc[nt][3];
        *(float2*)&g_po[((size_t)split * M_ + row0) * H_ + nt * 8 + 2 * tg] = v0;
        *(float2*)&g_po[((size_t)split * M_ + row1) * H_ + nt * 8 + 2 * tg] = v1;
    }
    if (tg == 0) {
        g_pm[(size_t)split * M_ + row0] = m0r;
        g_pl[(size_t)split * M_ + row0] = l0;
        g_pm[(size_t)split * M_ + row1] = m1r;
        g_pl[(size_t)split * M_ + row1] = l1;
    }
}

// ---------------- split combine ----------------------------------------------
__global__ __launch_bounds__(256) void combine_kernel(float* __restrict__ out)
{
    const int qg = blockIdx.x * 4 + (threadIdx.x >> 6);
    const int d  = threadIdx.x & 63;

    float mv[NS], lv[NS];
    float M = -1e30f;
    #pragma unroll
    for (int s = 0; s < NS; s++) {
        mv[s] = g_pm[(size_t)s * M_ + qg];
        lv[s] = g_pl[(size_t)s * M_ + qg];
        M = fmaxf(M, mv[s]);
    }
    float L = 0.0f, acc = 0.0f;
    #pragma unroll
    for (int s = 0; s < NS; s++) {
        float w = __expf(mv[s] - M);
        L += w * lv[s];
        acc += w * g_po[((size_t)s * M_ + qg) * H_ + d];
    }
    out[(size_t)qg * H_ + d] = acc / L;
}

// ---------------- launch ------------------------------------------------------
extern "C" void kernel_launch(void* const* d_in, const int* in_sizes, int n_in,
                              void* d_out, int out_size)
{
    const float* x  = (const float*)d_in[0];
    const float* Wk = (const float*)d_in[1];
    const float* Wq = (const float*)d_in[2];
    const float* Wv = (const float*)d_in[3];
    float* out = (float*)d_out;

    proj_fused_kernel<<<M_ / BM, 256>>>(x, Wk, Wq, Wv);
    attn_mma_kernel<<<dim3(S_ / QB2, B_, NS), 128>>>();
    combine_kernel<<<M_ / 4, 256>>>(out);
}